// round 16
// baseline (speedup 1.0000x reference)
#include <cuda_runtime.h>
#include <cuda_bf16.h>
#include <stdint.h>
#include <math.h>

#define NGRAPH 4096
#define NPG 32
#define NNODES (NGRAPH*NPG)      // 131072
#define FIN 256
#define FH 512
#define DOUT 164
#define NB 4
#define NPAD 192
#define APPEND_SZ ((size_t)NNODES*(DOUT-NB))
#define CONNECT_SZ ((size_t)NNODES*NB)

// ---------------- scratch (device globals; no allocation) ----------------
__device__ float g_Xend[(size_t)NGRAPH*FIN];
__device__ uint16_t g_Xhi[(size_t)NNODES*FIN];  // bf16 of X
__device__ uint16_t g_H[(size_t)NNODES*FH];     // H stored as bf16
__device__ float g_Hc[(size_t)NGRAPH*FH];       // per-graph Xend@W2^T contribution
__device__ float g_Hend[(size_t)NGRAPH*FH];
__device__ float g_part[(size_t)1024*2*FH];
__device__ float g_parte[(size_t)32*2*FH];
__device__ float g_bnA[FH], g_bnB[FH];
__device__ float g_bnAe[FH], g_bnBe[FH];
__device__ float g_Xxe[NGRAPH];
__device__ uint16_t g_Whi[(size_t)FH*FH];       // bf16 of W_h (full [512x512])
__device__ uint16_t g_Wxhi[(size_t)NPAD*FH];    // bf16 of padded W_x [192x512]
__device__ uint16_t g_Wchi[(size_t)1024*FIN];   // combined [Wh2;Wht] split [1024x256]
__device__ uint16_t g_Wclo[(size_t)1024*FIN];

// ================= portable tensor-core helpers (sm_80+ PTX) =================
__device__ __forceinline__ uint32_t smem_u32(const void* p){
    uint32_t a;
    asm("{ .reg .u64 t; cvta.to.shared.u64 t, %1; cvt.u32.u64 %0, t; }" : "=r"(a) : "l"(p));
    return a;
}
__device__ __forceinline__ void ldmA(uint32_t* a, uint32_t addr){
    asm volatile("ldmatrix.sync.aligned.m8n8.x4.shared.b16 {%0,%1,%2,%3}, [%4];"
        : "=r"(a[0]), "=r"(a[1]), "=r"(a[2]), "=r"(a[3]) : "r"(addr));
}
__device__ __forceinline__ void ldmB(uint32_t* b, uint32_t addr){
    asm volatile("ldmatrix.sync.aligned.m8n8.x4.shared.b16 {%0,%1,%2,%3}, [%4];"
        : "=r"(b[0]), "=r"(b[1]), "=r"(b[2]), "=r"(b[3]) : "r"(addr));
}
__device__ __forceinline__ void mma_bf(float* c, const uint32_t* a, const uint32_t* b){
    asm volatile("mma.sync.aligned.m16n8k16.row.col.f32.bf16.bf16.f32 "
        "{%0,%1,%2,%3}, {%4,%5,%6,%7}, {%8,%9}, {%0,%1,%2,%3};"
        : "+f"(c[0]), "+f"(c[1]), "+f"(c[2]), "+f"(c[3])
        : "r"(a[0]), "r"(a[1]), "r"(a[2]), "r"(a[3]), "r"(b[0]), "r"(b[1]));
}
#define CPA16(dst, src) asm volatile("cp.async.cg.shared.global [%0], [%1], 16;" :: "r"(dst), "l"(src))
#define CPC()  asm volatile("cp.async.commit_group;" ::: "memory")
#define CPW0() asm volatile("cp.async.wait_group 0;" ::: "memory")
#define CPW1() asm volatile("cp.async.wait_group 1;" ::: "memory")

__device__ __forceinline__ void split_bf(float v, uint16_t &h, uint16_t &l){
    __nv_bfloat16 hb = __float2bfloat16(v);
    float r = v - __bfloat162float(hb);
    h = __bfloat16_as_ushort(hb);
    l = __bfloat16_as_ushort(__float2bfloat16(r));
}
__device__ __forceinline__ uint32_t pack2(uint16_t a, uint16_t b){
    return (uint32_t)a | ((uint32_t)b << 16);
}
__device__ __forceinline__ uint16_t f2b(float v){
    return __bfloat16_as_ushort(__float2bfloat16(v));
}

// ==== k_prep: weight conversion (blocks 0-1023) + per-graph mean & X bf16 (1024-5119) ====
__global__ void k_prep(const float* __restrict__ X,  const float* __restrict__ Wh,
                       const float* __restrict__ Wx, const float* __restrict__ Wht)
{
    int bid = blockIdx.x;
    if (bid < 1024) {
        int i = bid*256 + threadIdx.x;         // 0 .. 262143
        if (i < FH*FH) g_Whi[i] = f2b(Wh[i]);
        if (i < NPAD*FH) {
            int r = i >> 9;
            g_Wxhi[i] = f2b((r < DOUT) ? Wx[i] : 0.f);
        }
        {   // combined pre-GEMM weights: rows 0-511 = Wh[:,256:512], rows 512-1023 = Wht
            int n = i >> 8, k = i & 255;
            float v = (n < FH) ? Wh[(size_t)n*FH + FIN + k] : Wht[(size_t)(n-FH)*FIN + k];
            uint16_t h,l; split_bf(v, h, l);
            g_Wchi[i] = h; g_Wclo[i] = l;
        }
    } else {
        int g = bid - 1024;                    // 0 .. 4095
        int c = threadIdx.x;                   // one column each (FIN=256)
        const float* xb = X + (size_t)g*NPG*FIN + c;
        uint16_t* xh = g_Xhi + (size_t)g*NPG*FIN + c;
        float s = 0.f;
#pragma unroll
        for (int r = 0; r < NPG; r++) {
            float v = xb[(size_t)r*FIN];
            s += v;
            xh[(size_t)r*FIN] = f2b(v);
        }
        g_Xend[(size_t)g*FIN + c] = s * (1.0f/NPG);
    }
}

// ========== pre-GEMM (MMA, 3-term): [Hc | Hend] = Xend @ [Wh2 ; Wht]^T ==========
// n-blocks 2,3 (Hend) also emit fused BN partial column stats.
#define SA 80
#define STGP 61440   // Ahi 10240 | Alo 10240 | Bhi 20480 | Blo 20480

__global__ __launch_bounds__(256,1) void k_pre_mma()
{
    extern __shared__ char sb[];
    __shared__ float sS[4][256], sQ[4][256];
    const int tid = threadIdx.x, lane = tid & 31, wid = tid >> 5;
    const int wm = wid >> 1, wn = wid & 1;
    const int n0 = blockIdx.x * 256, m0 = blockIdx.y * 128;
    const uint32_t sbu = smem_u32(sb);

    float acc[2][16][4];
#pragma unroll
    for (int a=0;a<2;a++)
#pragma unroll
        for (int b=0;b<16;b++)
#pragma unroll
            for (int d=0;d<4;d++) acc[a][b][d]=0.f;

    const uint32_t a_lo = (uint32_t)((lane & 15)*SA + (lane >> 4)*16);
    const int bg = lane >> 3;
    const uint32_t b_lo = (uint32_t)(((((bg>>1)<<3) + (lane&7))*SA) + (bg&1)*16);

    float4 va[4];
    auto loadA = [&](int ks){
        const int k0 = ks*32;
#pragma unroll
        for (int i=0;i<4;i++){
            int idx = tid + i*256;
            int r = idx >> 3, c4 = (idx & 7) << 2;
            va[i] = *(const float4*)(g_Xend + (size_t)(m0+r)*FIN + (k0 + c4));
        }
    };
    auto stsA = [&](int ks){
        const int s = ks & 1;
#pragma unroll
        for (int i=0;i<4;i++){
            int idx = tid + i*256;
            int r = idx >> 3, c4 = (idx & 7) << 2;
            int byte = r*SA + (c4<<1);
            uint16_t h0,h1,h2,h3,l0,l1,l2,l3;
            split_bf(va[i].x,h0,l0); split_bf(va[i].y,h1,l1);
            split_bf(va[i].z,h2,l2); split_bf(va[i].w,h3,l3);
            *(uint2*)(sb + s*STGP + byte)         = make_uint2(pack2(h0,h1), pack2(h2,h3));
            *(uint2*)(sb + s*STGP + 10240 + byte) = make_uint2(pack2(l0,l1), pack2(l2,l3));
        }
    };
    auto issueB = [&](int ks){
        const int s = ks & 1, k0 = ks*32;
        const uint32_t Bh = sbu + s*STGP + 20480, Bl = Bh + 20480;
#pragma unroll
        for (int j=0;j<4;j++){
            int idx = tid + j*256;
            int r = idx >> 2, ch = idx & 3;
            uint32_t d = (uint32_t)(r*SA + (ch<<4));
            CPA16(Bh + d, g_Wchi + (size_t)(n0+r)*FIN + k0 + (ch<<3));
            CPA16(Bl + d, g_Wclo + (size_t)(n0+r)*FIN + k0 + (ch<<3));
        }
    };
    auto compute = [&](int s){
        const uint32_t Ah = sbu + s*STGP, Al = Ah + 10240, Bh = Ah + 20480, Bl = Ah + 40960;
#pragma unroll
        for (int kk=0; kk<2; kk++){
            uint32_t aH[2][4], aL[2][4];
#pragma unroll
            for (int mt=0; mt<2; mt++){
                uint32_t off = (uint32_t)((wm*32 + mt*16)*SA + kk*32) + a_lo;
                ldmA(aH[mt], Ah + off);
                ldmA(aL[mt], Al + off);
            }
#pragma unroll
            for (int np=0; np<8; np++){
                uint32_t boff = (uint32_t)((wn*128 + np*16)*SA + kk*32) + b_lo;
                uint32_t bH[4], bL[4];
                ldmB(bH, Bh + boff);
                ldmB(bL, Bl + boff);
#pragma unroll
                for (int h=0; h<2; h++)
#pragma unroll
                    for (int mt=0; mt<2; mt++){
                        float* C = acc[mt][np*2+h];
                        mma_bf(C, aH[mt], &bH[h*2]);
                        mma_bf(C, aH[mt], &bL[h*2]);
                        mma_bf(C, aL[mt], &bH[h*2]);
                    }
            }
        }
    };

    loadA(0); issueB(0); CPC(); stsA(0);
    for (int ks=0; ks<8; ks++){
        CPW0(); __syncthreads();
        if (ks < 7){ loadA(ks+1); issueB(ks+1); CPC(); }
        compute(ks & 1);
        if (ks < 7) stsA(ks+1);
    }

    float* base = (n0 < FH) ? (g_Hc + n0) : (g_Hend + (n0 - FH));
#pragma unroll
    for (int mt=0; mt<2; mt++)
#pragma unroll
        for (int nt=0; nt<16; nt++){
            int R  = m0 + wm*32 + mt*16 + (lane>>2);
            int Cl = wn*128 + nt*8 + ((lane&3)<<1);
            *(float2*)(base + (size_t)R*FH + Cl)     = make_float2(acc[mt][nt][0], acc[mt][nt][1]);
            *(float2*)(base + (size_t)(R+8)*FH + Cl) = make_float2(acc[mt][nt][2], acc[mt][nt][3]);
        }

    // fused BN partial stats for the end-branch (Hend columns only)
    if (n0 >= FH) {
#pragma unroll
        for (int nt=0; nt<16; nt++){
            float s0=0.f,s1=0.f,q0=0.f,q1=0.f;
#pragma unroll
            for (int mt=0; mt<2; mt++){
                s0 += acc[mt][nt][0] + acc[mt][nt][2];
                s1 += acc[mt][nt][1] + acc[mt][nt][3];
                q0 += acc[mt][nt][0]*acc[mt][nt][0] + acc[mt][nt][2]*acc[mt][nt][2];
                q1 += acc[mt][nt][1]*acc[mt][nt][1] + acc[mt][nt][3]*acc[mt][nt][3];
            }
#pragma unroll
            for (int o=4;o<32;o<<=1){
                s0 += __shfl_xor_sync(0xffffffffu, s0, o);
                s1 += __shfl_xor_sync(0xffffffffu, s1, o);
                q0 += __shfl_xor_sync(0xffffffffu, q0, o);
                q1 += __shfl_xor_sync(0xffffffffu, q1, o);
            }
            if ((lane>>2)==0){
                int c = wn*128 + nt*8 + ((lane&3)<<1);
                sS[wm][c]=s0; sS[wm][c+1]=s1;
                sQ[wm][c]=q0; sQ[wm][c+1]=q1;
            }
        }
        __syncthreads();
        {
            int c = tid;    // 0..255, global Hend column = (n0-FH)+c
            float s = sS[0][c]+sS[1][c]+sS[2][c]+sS[3][c];
            float q = sQ[0][c]+sQ[1][c]+sQ[2][c]+sQ[3][c];
            int col = (n0 - FH) + c;
            g_parte[(size_t)blockIdx.y*2*FH + col]      = s;
            g_parte[(size_t)blockIdx.y*2*FH + FH + col] = q;
        }
    }
}

// === GEMM1 (1-term bf16): H = X @ W1^T + Hc[g]. 128x128, 3-stage, 3 CTA/SM ===
#define STG1 20480   // A 10240 | B 10240

__global__ __launch_bounds__(256,3) void k_gemm1_mma()
{
    extern __shared__ char sb[];
    __shared__ float sS[4][128], sQ[4][128];
    __shared__ float s_hc[4][128];
    const int tid = threadIdx.x, lane = tid & 31, wid = tid >> 5;
    const int wm = wid >> 1, wn = wid & 1;          // 4 M-warps x 2 N-warps (64 cols)
    const int n0 = blockIdx.x * 128, m0 = blockIdx.y * 128;
    const uint32_t sbu = smem_u32(sb);

    float acc[2][8][4];
#pragma unroll
    for (int a=0;a<2;a++)
#pragma unroll
        for (int b=0;b<8;b++)
#pragma unroll
            for (int d=0;d<4;d++) acc[a][b][d]=0.f;

    const uint32_t a_lo = (uint32_t)((lane & 15)*SA + (lane >> 4)*16);
    const int bg = lane >> 3;
    const uint32_t b_lo = (uint32_t)(((((bg>>1)<<3) + (lane&7))*SA) + (bg&1)*16);

    auto issue = [&](int ks){
        const int s = ks % 3, k0 = ks*32;
        const uint32_t Ah = sbu + s*STG1, Bh = Ah + 10240;
#pragma unroll
        for (int j=0;j<2;j++){               // A: 128 rows x 4 chunks
            int idx = tid + j*256;
            int r = idx >> 2, ch = idx & 3;
            CPA16(Ah + (uint32_t)(r*SA + (ch<<4)), g_Xhi + (size_t)(m0+r)*FIN + k0 + (ch<<3));
        }
#pragma unroll
        for (int j=0;j<2;j++){               // B: 128 rows x 4 chunks
            int idx = tid + j*256;
            int r = idx >> 2, ch = idx & 3;
            CPA16(Bh + (uint32_t)(r*SA + (ch<<4)), g_Whi + (size_t)(n0+r)*FH + k0 + (ch<<3));
        }
    };
    auto compute = [&](int s){
        const uint32_t Ah = sbu + s*STG1, Bh = Ah + 10240;
#pragma unroll
        for (int kk=0; kk<2; kk++){
            uint32_t aH[2][4];
#pragma unroll
            for (int mt=0; mt<2; mt++){
                uint32_t off = (uint32_t)((wm*32 + mt*16)*SA + kk*32) + a_lo;
                ldmA(aH[mt], Ah + off);
            }
#pragma unroll
            for (int np=0; np<4; np++){
                uint32_t boff = (uint32_t)((wn*64 + np*16)*SA + kk*32) + b_lo;
                uint32_t bH[4];
                ldmB(bH, Bh + boff);
#pragma unroll
                for (int h=0; h<2; h++)
#pragma unroll
                    for (int mt=0; mt<2; mt++)
                        mma_bf(acc[mt][np*2+h], aH[mt], &bH[h*2]);
            }
        }
    };

    issue(0); CPC(); issue(1); CPC();
    for (int ks=0; ks<8; ks++){
        if (ks < 6) CPW1(); else CPW0();
        __syncthreads();
        if (ks < 6){ issue(ks+2); CPC(); }
        compute(ks % 3);
    }
    __syncthreads();

    // per-graph contribution Hc -> smem (4 graphs x 128 cols)
    for (int i = tid; i < 4*128; i += 256) {
        int gg = i >> 7, cc = i & 127;
        s_hc[gg][cc] = g_Hc[(size_t)((m0>>5)+gg)*FH + n0 + cc];
    }
    __syncthreads();

    // add Hc, store H (bf16), fused BN column stats (fp32)
#pragma unroll
    for (int mt=0; mt<2; mt++)
#pragma unroll
        for (int nt=0; nt<8; nt++){
            int Cl = wn*64 + nt*8 + ((lane&3)<<1);
            float c0 = s_hc[wm][Cl], c1 = s_hc[wm][Cl+1];
            acc[mt][nt][0] += c0; acc[mt][nt][1] += c1;
            acc[mt][nt][2] += c0; acc[mt][nt][3] += c1;
            int R = m0 + wm*32 + mt*16 + (lane>>2);
            *(uint32_t*)(g_H + (size_t)R*FH + n0 + Cl)     = pack2(f2b(acc[mt][nt][0]), f2b(acc[mt][nt][1]));
            *(uint32_t*)(g_H + (size_t)(R+8)*FH + n0 + Cl) = pack2(f2b(acc[mt][nt][2]), f2b(acc[mt][nt][3]));
        }
#pragma unroll
    for (int nt=0; nt<8; nt++){
        float s0=0.f,s1=0.f,q0=0.f,q1=0.f;
#pragma unroll
        for (int mt=0; mt<2; mt++){
            s0 += acc[mt][nt][0] + acc[mt][nt][2];
            s1 += acc[mt][nt][1] + acc[mt][nt][3];
            q0 += acc[mt][nt][0]*acc[mt][nt][0] + acc[mt][nt][2]*acc[mt][nt][2];
            q1 += acc[mt][nt][1]*acc[mt][nt][1] + acc[mt][nt][3]*acc[mt][nt][3];
        }
#pragma unroll
        for (int o=4;o<32;o<<=1){
            s0 += __shfl_xor_sync(0xffffffffu, s0, o);
            s1 += __shfl_xor_sync(0xffffffffu, s1, o);
            q0 += __shfl_xor_sync(0xffffffffu, q0, o);
            q1 += __shfl_xor_sync(0xffffffffu, q1, o);
        }
        if ((lane>>2)==0){
            int c = wn*64 + nt*8 + ((lane&3)<<1);
            sS[wm][c]=s0; sS[wm][c+1]=s1;
            sQ[wm][c]=q0; sQ[wm][c+1]=q1;
        }
    }
    __syncthreads();
    if (tid < 128) {
        int c = tid;
        float s = sS[0][c]+sS[1][c]+sS[2][c]+sS[3][c];
        float q = sQ[0][c]+sQ[1][c]+sQ[2][c]+sQ[3][c];
        g_part[(size_t)blockIdx.y*2*FH + n0 + c]      = s;
        g_part[(size_t)blockIdx.y*2*FH + FH + n0 + c] = q;
    }
}

// ---------------- combined BN reduce (blocks 0-511: H, 512-1023: Hend) ----------------
__global__ void k_bn_both(const float* __restrict__ gm_h, const float* __restrict__ bt_h,
                          const float* __restrict__ gm_t, const float* __restrict__ bt_t)
{
    int cb = blockIdx.x;
    int mode = (cb >= FH);
    int c = mode ? cb - FH : cb;
    int t = threadIdx.x;
    int nblocks = mode ? (NGRAPH/128) : (NNODES/128);
    float invN   = mode ? (1.0f/(float)NGRAPH) : (1.0f/(float)NNODES);
    const float* part  = mode ? g_parte : g_part;
    const float* gamma = mode ? gm_t : gm_h;
    const float* beta  = mode ? bt_t : bt_h;

    float s = 0.f, q = 0.f;
    for (int i = t; i < nblocks; i += 256) {
        s += part[(size_t)i*2*FH + c];
        q += part[(size_t)i*2*FH + FH + c];
    }
    __shared__ float rs[256], rq[256];
    rs[t] = s; rq[t] = q; __syncthreads();
    for (int o = 128; o > 0; o >>= 1) {
        if (t < o) { rs[t] += rs[t+o]; rq[t] += rq[t+o]; }
        __syncthreads();
    }
    if (t == 0) {
        float mean = rs[0] * invN;
        float var  = rq[0] * invN - mean*mean;
        float a    = gamma[c] * rsqrtf(var + 1e-5f);
        float bb   = beta[c] - mean * a;
        if (mode) { g_bnAe[c] = a; g_bnBe[c] = bb; }
        else      { g_bnA[c]  = a; g_bnB[c]  = bb; }
    }
}

// ---------------- end branch exp-dot ----------------
__global__ void k_endx(const float* __restrict__ Wxt, const float* __restrict__ bxt)
{
    int g = blockIdx.x;
    int t = threadIdx.x;
    float s = 0.f;
    for (int k = t; k < FH; k += 128) {
        float v = fmaxf(fmaf(g_Hend[(size_t)g*FH + k], g_bnAe[k], g_bnBe[k]), 0.f);
        s = fmaf(v, Wxt[k], s);
    }
    __shared__ float red[128];
    red[t] = s; __syncthreads();
    for (int o = 64; o > 0; o >>= 1) {
        if (t < o) red[t] += red[t+o];
        __syncthreads();
    }
    if (t == 0) g_Xxe[g] = expf(red[0] + bxt[0]);
}

// ===== GEMM2 (1-term): tile 128x192, warp grid 2Mx4N (warp 64x48), 3-stage, 2 CTA/SM =====
#define STG2 25600   // A 10240 | B 15360

__global__ __launch_bounds__(256,2) void k_gemm2_mma(const float* __restrict__ bx,
                                                     float* __restrict__ out)
{
    extern __shared__ char sb[];
    __shared__ float s_sa[FH], s_sb[FH], s_bx[DOUT];
    __shared__ float srow[4][128];
    __shared__ float s_inv[4];
    const int tid = threadIdx.x, lane = tid & 31, wid = tid >> 5;
    const int wm = wid >> 2, wn = wid & 3;          // 2 M-warps(64 rows) x 4 N-warps(48 cols)
    const int m0 = blockIdx.x * 128;
    const uint32_t sbu = smem_u32(sb);

    for (int i = tid; i < FH; i += 256) { s_sa[i] = g_bnA[i]; s_sb[i] = g_bnB[i]; }
    if (tid < DOUT) s_bx[tid] = bx[tid];
    __syncthreads();

    float acc[4][6][4];
#pragma unroll
    for (int a=0;a<4;a++)
#pragma unroll
        for (int b=0;b<6;b++)
#pragma unroll
            for (int d=0;d<4;d++) acc[a][b][d]=0.f;

    const uint32_t a_lo = (uint32_t)((lane & 15)*SA + (lane >> 4)*16);
    const int bg = lane >> 3;
    const uint32_t b_lo = (uint32_t)(((((bg>>1)<<3) + (lane&7))*SA) + (bg&1)*16);

    uint4 va[2];
    auto loadA = [&](int ks){
        const int k0 = ks*32;
#pragma unroll
        for (int i=0;i<2;i++){
            int idx = tid + i*256;           // 128 rows x 4 chunks = 512
            int r = idx >> 2, ch = idx & 3;
            va[i] = *(const uint4*)(g_H + (size_t)(m0+r)*FH + k0 + (ch<<3));
        }
    };
    auto stsA = [&](int ks){
        const int s = ks % 3, k0 = ks*32;
#pragma unroll
        for (int i=0;i<2;i++){
            int idx = tid + i*256;
            int r = idx >> 2, ch = idx & 3;
            uint32_t w[4];
            const uint32_t* vw = (const uint32_t*)&va[i];
#pragma unroll
            for (int j=0;j<4;j++){
                int k = k0 + (ch<<3) + j*2;
                float f0 = __uint_as_float((vw[j] & 0xffffu) << 16);
                float f1 = __uint_as_float(vw[j] & 0xffff0000u);
                float x0 = fmaxf(fmaf(f0, s_sa[k],   s_sb[k]),   0.f);
                float x1 = fmaxf(fmaf(f1, s_sa[k+1], s_sb[k+1]), 0.f);
                w[j] = pack2(f2b(x0), f2b(x1));
            }
            *(uint4*)(sb + s*STG2 + r*SA + (ch<<4)) = make_uint4(w[0],w[1],w[2],w[3]);
        }
    };
    auto issueB = [&](int ks){
        const int s = ks % 3, k0 = ks*32;
        const uint32_t Bh = sbu + s*STG2 + 10240;
#pragma unroll
        for (int j=0;j<3;j++){
            int idx = tid + j*256;           // 192 rows x 4 chunks = 768
            int r = idx >> 2, ch = idx & 3;
            CPA16(Bh + (uint32_t)(r*SA + (ch<<4)), g_Wxhi + (size_t)r*FH + k0 + (ch<<3));
        }
    };
    auto compute = [&](int s){
        const uint32_t Ah = sbu + s*STG2, Bh = Ah + 10240;
#pragma unroll
        for (int kk=0; kk<2; kk++){
            uint32_t aH[4][4];
#pragma unroll
            for (int mt=0; mt<4; mt++){
                uint32_t off = (uint32_t)((wm*64 + mt*16)*SA + kk*32) + a_lo;
                ldmA(aH[mt], Ah + off);
            }
#pragma unroll
            for (int nb=0; nb<3; nb++){
                uint32_t boff = (uint32_t)((wn*48 + nb*16)*SA + kk*32) + b_lo;
                uint32_t bH[4];
                ldmB(bH, Bh + boff);
#pragma unroll
                for (int h=0; h<2; h++)
#pragma unroll
                    for (int mt=0; mt<4; mt++)
                        mma_bf(acc[mt][nb*2+h], aH[mt], &bH[h*2]);
            }
        }
    };

    loadA(0); issueB(0); CPC(); stsA(0);
    loadA(1); issueB(1); CPC(); stsA(1);
    for (int ks=0; ks<16; ks++){
        if (ks < 14) CPW1(); else CPW0();
        __syncthreads();
        if (ks < 14){ loadA(ks+2); issueB(ks+2); CPC(); }
        compute(ks % 3);
        if (ks < 14) stsA(ks+2);
    }
    __syncthreads();

    // ---- fused epilogue: exp(+bias), per-graph softmax sums, normalize, scatter ----
    float rsum[4][2] = {{0.f,0.f},{0.f,0.f},{0.f,0.f},{0.f,0.f}};
#pragma unroll
    for (int mt=0; mt<4; mt++)
#pragma unroll
        for (int nt=0; nt<6; nt++){
            int cg = wn*48 + nt*8 + ((lane&3)<<1);
            if (cg < DOUT){
                float e0 = expf(acc[mt][nt][0] + s_bx[cg]);
                float e1 = expf(acc[mt][nt][1] + s_bx[cg+1]);
                float e2 = expf(acc[mt][nt][2] + s_bx[cg]);
                float e3 = expf(acc[mt][nt][3] + s_bx[cg+1]);
                acc[mt][nt][0]=e0; acc[mt][nt][1]=e1;
                acc[mt][nt][2]=e2; acc[mt][nt][3]=e3;
                rsum[mt][0] += e0+e1;
                rsum[mt][1] += e2+e3;
            }
        }
#pragma unroll
    for (int mt=0;mt<4;mt++){
        rsum[mt][0] += __shfl_xor_sync(0xffffffffu, rsum[mt][0], 1);
        rsum[mt][0] += __shfl_xor_sync(0xffffffffu, rsum[mt][0], 2);
        rsum[mt][1] += __shfl_xor_sync(0xffffffffu, rsum[mt][1], 1);
        rsum[mt][1] += __shfl_xor_sync(0xffffffffu, rsum[mt][1], 2);
    }
    if ((lane&3)==0){
#pragma unroll
        for (int mt=0;mt<4;mt++){
            int r = wm*64 + mt*16 + (lane>>2);
            srow[wn][r]   = rsum[mt][0];
            srow[wn][r+8] = rsum[mt][1];
        }
    }
    __syncthreads();
    if (wid == 0){
#pragma unroll
        for (int g=0; g<4; g++){
            float v = srow[0][g*32 + lane] + srow[1][g*32 + lane]
                    + srow[2][g*32 + lane] + srow[3][g*32 + lane];
#pragma unroll
            for (int o=16;o;o>>=1) v += __shfl_xor_sync(0xffffffffu, v, o);
            if (lane == 0){
                int G = (m0>>5) + g;
                float xe = g_Xxe[G];
                float tot = v + xe;
                s_inv[g] = 1.0f/tot;
                out[APPEND_SZ + CONNECT_SZ + G] = xe/tot;
            }
        }
    }
    __syncthreads();
#pragma unroll
    for (int mt=0;mt<4;mt++){
        const float f = s_inv[wm*2 + (mt>>1)];
#pragma unroll
        for (int nt=0;nt<6;nt++){
            int cg = wn*48 + nt*8 + ((lane&3)<<1);
            if (cg < DOUT){
                int R0 = m0 + wm*64 + mt*16 + (lane>>2);
                int R1 = R0 + 8;
                float2 v0 = make_float2(acc[mt][nt][0]*f, acc[mt][nt][1]*f);
                float2 v1 = make_float2(acc[mt][nt][2]*f, acc[mt][nt][3]*f);
                if (cg < NB){
                    *(float2*)(out + APPEND_SZ + (size_t)R0*NB + cg) = v0;
                    *(float2*)(out + APPEND_SZ + (size_t)R1*NB + cg) = v1;
                } else {
                    *(float2*)(out + (size_t)R0*(DOUT-NB) + (cg-NB)) = v0;
                    *(float2*)(out + (size_t)R1*(DOUT-NB) + (cg-NB)) = v1;
                }
            }
        }
    }
}

// ---------------- launch ----------------
extern "C" void kernel_launch(void* const* d_in, const int* in_sizes, int n_in,
                              void* d_out, int out_size)
{
    const float* X    = (const float*)d_in[0];
    const float* W_h  = (const float*)d_in[3];
    const float* gm_h = (const float*)d_in[4];
    const float* bt_h = (const float*)d_in[5];
    const float* W_ht = (const float*)d_in[6];
    const float* gm_t = (const float*)d_in[7];
    const float* bt_t = (const float*)d_in[8];
    const float* W_x  = (const float*)d_in[9];
    const float* b_x  = (const float*)d_in[10];
    const float* W_xt = (const float*)d_in[11];
    const float* b_xt = (const float*)d_in[12];
    float* out = (float*)d_out;

    cudaFuncSetAttribute(k_pre_mma,   cudaFuncAttributeMaxDynamicSharedMemorySize, 2*STGP);
    cudaFuncSetAttribute(k_gemm1_mma, cudaFuncAttributeMaxDynamicSharedMemorySize, 3*STG1);
    cudaFuncSetAttribute(k_gemm2_mma, cudaFuncAttributeMaxDynamicSharedMemorySize, 3*STG2);

    // weight conversion + per-graph mean + X bf16 (one merged grid)
    k_prep<<<1024 + NGRAPH, 256>>>(X, W_h, W_x, W_ht);

    // [Hc | Hend] = Xend @ [Wh2 ; Wht]^T (3-term) with fused end-branch stats
    k_pre_mma<<<dim3(4, NGRAPH/128), 256, 2*STGP>>>();

    // H = X @ W1^T + Hc[g]  (bf16 store) + fused BN partial stats (K=256)
    k_gemm1_mma<<<dim3(4, NNODES/128), 256, 3*STG1>>>();

    // both BN reductions in one launch
    k_bn_both<<<2*FH, 256>>>(gm_h, bt_h, gm_t, bt_t);

    // end-branch exp-dot
    k_endx<<<NGRAPH, 128>>>(W_xt, b_xt);

    // X_x GEMM (bf16) + exp + per-graph softmax + scatter
    k_gemm2_mma<<<NNODES/128, 256, 3*STG2>>>(b_x, out);
}

// round 17
// speedup vs baseline: 1.4266x; 1.4266x over previous
#include <cuda_runtime.h>
#include <cuda_bf16.h>
#include <stdint.h>
#include <math.h>

#define NGRAPH 4096
#define NPG 32
#define NNODES (NGRAPH*NPG)      // 131072
#define FIN 256
#define FH 512
#define DOUT 164
#define NB 4
#define NPAD 192
#define APPEND_SZ ((size_t)NNODES*(DOUT-NB))
#define CONNECT_SZ ((size_t)NNODES*NB)

// ---------------- scratch (device globals; no allocation) ----------------
__device__ float g_Xend[(size_t)NGRAPH*FIN];
__device__ uint16_t g_Xhi[(size_t)NNODES*FIN];  // bf16 of X
__device__ uint16_t g_H[(size_t)NNODES*FH];     // H stored as bf16
__device__ float g_Hc[(size_t)NGRAPH*FH];       // per-graph Xend@W2^T contribution
__device__ float g_Hend[(size_t)NGRAPH*FH];
__device__ float g_part[(size_t)1024*2*FH];
__device__ float g_parte[(size_t)32*2*FH];
__device__ float g_bnA[FH], g_bnB[FH];
__device__ float g_bnAe[FH], g_bnBe[FH];
__device__ float g_Xxe[NGRAPH];
__device__ uint16_t g_Whi[(size_t)FH*FH];       // bf16 of W_h (full [512x512])
__device__ uint16_t g_Wxhi[(size_t)NPAD*FH];    // bf16 of padded W_x [192x512]
__device__ uint16_t g_Wchi[(size_t)1024*FIN];   // combined [Wh2;Wht] bf16 [1024x256]

// ================= portable tensor-core helpers (sm_80+ PTX) =================
__device__ __forceinline__ uint32_t smem_u32(const void* p){
    uint32_t a;
    asm("{ .reg .u64 t; cvta.to.shared.u64 t, %1; cvt.u32.u64 %0, t; }" : "=r"(a) : "l"(p));
    return a;
}
__device__ __forceinline__ void ldmA(uint32_t* a, uint32_t addr){
    asm volatile("ldmatrix.sync.aligned.m8n8.x4.shared.b16 {%0,%1,%2,%3}, [%4];"
        : "=r"(a[0]), "=r"(a[1]), "=r"(a[2]), "=r"(a[3]) : "r"(addr));
}
__device__ __forceinline__ void ldmB(uint32_t* b, uint32_t addr){
    asm volatile("ldmatrix.sync.aligned.m8n8.x4.shared.b16 {%0,%1,%2,%3}, [%4];"
        : "=r"(b[0]), "=r"(b[1]), "=r"(b[2]), "=r"(b[3]) : "r"(addr));
}
__device__ __forceinline__ void mma_bf(float* c, const uint32_t* a, const uint32_t* b){
    asm volatile("mma.sync.aligned.m16n8k16.row.col.f32.bf16.bf16.f32 "
        "{%0,%1,%2,%3}, {%4,%5,%6,%7}, {%8,%9}, {%0,%1,%2,%3};"
        : "+f"(c[0]), "+f"(c[1]), "+f"(c[2]), "+f"(c[3])
        : "r"(a[0]), "r"(a[1]), "r"(a[2]), "r"(a[3]), "r"(b[0]), "r"(b[1]));
}
#define CPA16(dst, src) asm volatile("cp.async.cg.shared.global [%0], [%1], 16;" :: "r"(dst), "l"(src))
#define CPC()  asm volatile("cp.async.commit_group;" ::: "memory")
#define CPW0() asm volatile("cp.async.wait_group 0;" ::: "memory")
#define CPW1() asm volatile("cp.async.wait_group 1;" ::: "memory")
#define CPW2() asm volatile("cp.async.wait_group 2;" ::: "memory")

__device__ __forceinline__ void split_bf(float v, uint16_t &h, uint16_t &l){
    __nv_bfloat16 hb = __float2bfloat16(v);
    float r = v - __bfloat162float(hb);
    h = __bfloat16_as_ushort(hb);
    l = __bfloat16_as_ushort(__float2bfloat16(r));
}
__device__ __forceinline__ uint32_t pack2(uint16_t a, uint16_t b){
    return (uint32_t)a | ((uint32_t)b << 16);
}
__device__ __forceinline__ uint16_t f2b(float v){
    return __bfloat16_as_ushort(__float2bfloat16(v));
}

// ==== k_prep: weight conversion (blocks 0-1023) + per-graph mean & X bf16 (1024-5119) ====
__global__ void k_prep(const float* __restrict__ X,  const float* __restrict__ Wh,
                       const float* __restrict__ Wx, const float* __restrict__ Wht)
{
    int bid = blockIdx.x;
    if (bid < 1024) {
        int i = bid*256 + threadIdx.x;         // 0 .. 262143
        if (i < FH*FH) g_Whi[i] = f2b(Wh[i]);
        if (i < NPAD*FH) {
            int r = i >> 9;
            g_Wxhi[i] = f2b((r < DOUT) ? Wx[i] : 0.f);
        }
        {   // combined pre-GEMM weights: rows 0-511 = Wh[:,256:512], rows 512-1023 = Wht
            int n = i >> 8, k = i & 255;
            float v = (n < FH) ? Wh[(size_t)n*FH + FIN + k] : Wht[(size_t)(n-FH)*FIN + k];
            g_Wchi[i] = f2b(v);
        }
    } else {
        int g = bid - 1024;                    // 0 .. 4095
        int c = threadIdx.x;                   // one column each (FIN=256)
        const float* xb = X + (size_t)g*NPG*FIN + c;
        uint16_t* xh = g_Xhi + (size_t)g*NPG*FIN + c;
        float s = 0.f;
#pragma unroll
        for (int r = 0; r < NPG; r++) {
            float v = xb[(size_t)r*FIN];
            s += v;
            xh[(size_t)r*FIN] = f2b(v);
        }
        g_Xend[(size_t)g*FIN + c] = s * (1.0f/NPG);
    }
}

// ========== pre-GEMM (MMA, 2-term: (Ahi+Alo)·Bhi): [Hc | Hend] = Xend @ [Wh2;Wht]^T ==========
// n-blocks 2,3 (Hend) also emit fused BN partial column stats.
#define SA 80
#define STGP 40960   // Ahi 10240 | Alo 10240 | Bhi 20480

__global__ __launch_bounds__(256,1) void k_pre_mma()
{
    extern __shared__ char sb[];
    __shared__ float sS[4][256], sQ[4][256];
    const int tid = threadIdx.x, lane = tid & 31, wid = tid >> 5;
    const int wm = wid >> 1, wn = wid & 1;
    const int n0 = blockIdx.x * 256, m0 = blockIdx.y * 128;
    const uint32_t sbu = smem_u32(sb);

    float acc[2][16][4];
#pragma unroll
    for (int a=0;a<2;a++)
#pragma unroll
        for (int b=0;b<16;b++)
#pragma unroll
            for (int d=0;d<4;d++) acc[a][b][d]=0.f;

    const uint32_t a_lo = (uint32_t)((lane & 15)*SA + (lane >> 4)*16);
    const int bg = lane >> 3;
    const uint32_t b_lo = (uint32_t)(((((bg>>1)<<3) + (lane&7))*SA) + (bg&1)*16);

    float4 va[4];
    auto loadA = [&](int ks){
        const int k0 = ks*32;
#pragma unroll
        for (int i=0;i<4;i++){
            int idx = tid + i*256;
            int r = idx >> 3, c4 = (idx & 7) << 2;
            va[i] = *(const float4*)(g_Xend + (size_t)(m0+r)*FIN + (k0 + c4));
        }
    };
    auto stsA = [&](int ks){
        const int s = ks & 1;
#pragma unroll
        for (int i=0;i<4;i++){
            int idx = tid + i*256;
            int r = idx >> 3, c4 = (idx & 7) << 2;
            int byte = r*SA + (c4<<1);
            uint16_t h0,h1,h2,h3,l0,l1,l2,l3;
            split_bf(va[i].x,h0,l0); split_bf(va[i].y,h1,l1);
            split_bf(va[i].z,h2,l2); split_bf(va[i].w,h3,l3);
            *(uint2*)(sb + s*STGP + byte)         = make_uint2(pack2(h0,h1), pack2(h2,h3));
            *(uint2*)(sb + s*STGP + 10240 + byte) = make_uint2(pack2(l0,l1), pack2(l2,l3));
        }
    };
    auto issueB = [&](int ks){
        const int s = ks & 1, k0 = ks*32;
        const uint32_t Bh = sbu + s*STGP + 20480;
#pragma unroll
        for (int j=0;j<4;j++){
            int idx = tid + j*256;
            int r = idx >> 2, ch = idx & 3;
            CPA16(Bh + (uint32_t)(r*SA + (ch<<4)), g_Wchi + (size_t)(n0+r)*FIN + k0 + (ch<<3));
        }
    };
    auto compute = [&](int s){
        const uint32_t Ah = sbu + s*STGP, Al = Ah + 10240, Bh = Ah + 20480;
#pragma unroll
        for (int kk=0; kk<2; kk++){
            uint32_t aH[2][4], aL[2][4];
#pragma unroll
            for (int mt=0; mt<2; mt++){
                uint32_t off = (uint32_t)((wm*32 + mt*16)*SA + kk*32) + a_lo;
                ldmA(aH[mt], Ah + off);
                ldmA(aL[mt], Al + off);
            }
#pragma unroll
            for (int np=0; np<8; np++){
                uint32_t boff = (uint32_t)((wn*128 + np*16)*SA + kk*32) + b_lo;
                uint32_t bH[4];
                ldmB(bH, Bh + boff);
#pragma unroll
                for (int h=0; h<2; h++)
#pragma unroll
                    for (int mt=0; mt<2; mt++){
                        float* C = acc[mt][np*2+h];
                        mma_bf(C, aH[mt], &bH[h*2]);
                        mma_bf(C, aL[mt], &bH[h*2]);
                    }
            }
        }
    };

    loadA(0); issueB(0); CPC(); stsA(0);
    for (int ks=0; ks<8; ks++){
        CPW0(); __syncthreads();
        if (ks < 7){ loadA(ks+1); issueB(ks+1); CPC(); }
        compute(ks & 1);
        if (ks < 7) stsA(ks+1);
    }

    float* base = (n0 < FH) ? (g_Hc + n0) : (g_Hend + (n0 - FH));
#pragma unroll
    for (int mt=0; mt<2; mt++)
#pragma unroll
        for (int nt=0; nt<16; nt++){
            int R  = m0 + wm*32 + mt*16 + (lane>>2);
            int Cl = wn*128 + nt*8 + ((lane&3)<<1);
            *(float2*)(base + (size_t)R*FH + Cl)     = make_float2(acc[mt][nt][0], acc[mt][nt][1]);
            *(float2*)(base + (size_t)(R+8)*FH + Cl) = make_float2(acc[mt][nt][2], acc[mt][nt][3]);
        }

    // fused BN partial stats for the end-branch (Hend columns only)
    if (n0 >= FH) {
#pragma unroll
        for (int nt=0; nt<16; nt++){
            float s0=0.f,s1=0.f,q0=0.f,q1=0.f;
#pragma unroll
            for (int mt=0; mt<2; mt++){
                s0 += acc[mt][nt][0] + acc[mt][nt][2];
                s1 += acc[mt][nt][1] + acc[mt][nt][3];
                q0 += acc[mt][nt][0]*acc[mt][nt][0] + acc[mt][nt][2]*acc[mt][nt][2];
                q1 += acc[mt][nt][1]*acc[mt][nt][1] + acc[mt][nt][3]*acc[mt][nt][3];
            }
#pragma unroll
            for (int o=4;o<32;o<<=1){
                s0 += __shfl_xor_sync(0xffffffffu, s0, o);
                s1 += __shfl_xor_sync(0xffffffffu, s1, o);
                q0 += __shfl_xor_sync(0xffffffffu, q0, o);
                q1 += __shfl_xor_sync(0xffffffffu, q1, o);
            }
            if ((lane>>2)==0){
                int c = wn*128 + nt*8 + ((lane&3)<<1);
                sS[wm][c]=s0; sS[wm][c+1]=s1;
                sQ[wm][c]=q0; sQ[wm][c+1]=q1;
            }
        }
        __syncthreads();
        {
            int c = tid;
            float s = sS[0][c]+sS[1][c]+sS[2][c]+sS[3][c];
            float q = sQ[0][c]+sQ[1][c]+sQ[2][c]+sQ[3][c];
            int col = (n0 - FH) + c;
            g_parte[(size_t)blockIdx.y*2*FH + col]      = s;
            g_parte[(size_t)blockIdx.y*2*FH + FH + col] = q;
        }
    }
}

// === GEMM1 (1-term bf16): H = X @ W1^T + Hc[g]. 128x128, 4-stage, 2 CTA/SM ===
#define STG1 20480   // A 10240 | B 10240

__global__ __launch_bounds__(256,2) void k_gemm1_mma()
{
    extern __shared__ char sb[];
    __shared__ float sS[4][128], sQ[4][128];
    __shared__ float s_hc[4][128];
    const int tid = threadIdx.x, lane = tid & 31, wid = tid >> 5;
    const int wm = wid >> 1, wn = wid & 1;          // 4 M-warps x 2 N-warps (64 cols)
    const int n0 = blockIdx.x * 128, m0 = blockIdx.y * 128;
    const uint32_t sbu = smem_u32(sb);

    float acc[2][8][4];
#pragma unroll
    for (int a=0;a<2;a++)
#pragma unroll
        for (int b=0;b<8;b++)
#pragma unroll
            for (int d=0;d<4;d++) acc[a][b][d]=0.f;

    const uint32_t a_lo = (uint32_t)((lane & 15)*SA + (lane >> 4)*16);
    const int bg = lane >> 3;
    const uint32_t b_lo = (uint32_t)(((((bg>>1)<<3) + (lane&7))*SA) + (bg&1)*16);

    auto issue = [&](int ks){
        const int s = ks & 3, k0 = ks*32;
        const uint32_t Ah = sbu + s*STG1, Bh = Ah + 10240;
#pragma unroll
        for (int j=0;j<2;j++){               // A: 128 rows x 4 chunks
            int idx = tid + j*256;
            int r = idx >> 2, ch = idx & 3;
            CPA16(Ah + (uint32_t)(r*SA + (ch<<4)), g_Xhi + (size_t)(m0+r)*FIN + k0 + (ch<<3));
        }
#pragma unroll
        for (int j=0;j<2;j++){               // B: 128 rows x 4 chunks
            int idx = tid + j*256;
            int r = idx >> 2, ch = idx & 3;
            CPA16(Bh + (uint32_t)(r*SA + (ch<<4)), g_Whi + (size_t)(n0+r)*FH + k0 + (ch<<3));
        }
    };
    auto compute = [&](int s){
        const uint32_t Ah = sbu + s*STG1, Bh = Ah + 10240;
#pragma unroll
        for (int kk=0; kk<2; kk++){
            uint32_t aH[2][4];
#pragma unroll
            for (int mt=0; mt<2; mt++){
                uint32_t off = (uint32_t)((wm*32 + mt*16)*SA + kk*32) + a_lo;
                ldmA(aH[mt], Ah + off);
            }
#pragma unroll
            for (int np=0; np<4; np++){
                uint32_t boff = (uint32_t)((wn*64 + np*16)*SA + kk*32) + b_lo;
                uint32_t bH[4];
                ldmB(bH, Bh + boff);
#pragma unroll
                for (int h=0; h<2; h++)
#pragma unroll
                    for (int mt=0; mt<2; mt++)
                        mma_bf(acc[mt][np*2+h], aH[mt], &bH[h*2]);
            }
        }
    };

    issue(0); CPC(); issue(1); CPC(); issue(2); CPC();
    for (int ks=0; ks<8; ks++){
        if (ks < 6) CPW2(); else if (ks == 6) CPW1(); else CPW0();
        __syncthreads();
        if (ks < 5){ issue(ks+3); CPC(); }
        compute(ks & 3);
    }
    __syncthreads();

    // per-graph contribution Hc -> smem (4 graphs x 128 cols)
    for (int i = tid; i < 4*128; i += 256) {
        int gg = i >> 7, cc = i & 127;
        s_hc[gg][cc] = g_Hc[(size_t)((m0>>5)+gg)*FH + n0 + cc];
    }
    __syncthreads();

    // add Hc, store H (bf16), fused BN column stats (fp32)
#pragma unroll
    for (int mt=0; mt<2; mt++)
#pragma unroll
        for (int nt=0; nt<8; nt++){
            int Cl = wn*64 + nt*8 + ((lane&3)<<1);
            float c0 = s_hc[wm][Cl], c1 = s_hc[wm][Cl+1];
            acc[mt][nt][0] += c0; acc[mt][nt][1] += c1;
            acc[mt][nt][2] += c0; acc[mt][nt][3] += c1;
            int R = m0 + wm*32 + mt*16 + (lane>>2);
            *(uint32_t*)(g_H + (size_t)R*FH + n0 + Cl)     = pack2(f2b(acc[mt][nt][0]), f2b(acc[mt][nt][1]));
            *(uint32_t*)(g_H + (size_t)(R+8)*FH + n0 + Cl) = pack2(f2b(acc[mt][nt][2]), f2b(acc[mt][nt][3]));
        }
#pragma unroll
    for (int nt=0; nt<8; nt++){
        float s0=0.f,s1=0.f,q0=0.f,q1=0.f;
#pragma unroll
        for (int mt=0; mt<2; mt++){
            s0 += acc[mt][nt][0] + acc[mt][nt][2];
            s1 += acc[mt][nt][1] + acc[mt][nt][3];
            q0 += acc[mt][nt][0]*acc[mt][nt][0] + acc[mt][nt][2]*acc[mt][nt][2];
            q1 += acc[mt][nt][1]*acc[mt][nt][1] + acc[mt][nt][3]*acc[mt][nt][3];
        }
#pragma unroll
        for (int o=4;o<32;o<<=1){
            s0 += __shfl_xor_sync(0xffffffffu, s0, o);
            s1 += __shfl_xor_sync(0xffffffffu, s1, o);
            q0 += __shfl_xor_sync(0xffffffffu, q0, o);
            q1 += __shfl_xor_sync(0xffffffffu, q1, o);
        }
        if ((lane>>2)==0){
            int c = wn*64 + nt*8 + ((lane&3)<<1);
            sS[wm][c]=s0; sS[wm][c+1]=s1;
            sQ[wm][c]=q0; sQ[wm][c+1]=q1;
        }
    }
    __syncthreads();
    if (tid < 128) {
        int c = tid;
        float s = sS[0][c]+sS[1][c]+sS[2][c]+sS[3][c];
        float q = sQ[0][c]+sQ[1][c]+sQ[2][c]+sQ[3][c];
        g_part[(size_t)blockIdx.y*2*FH + n0 + c]      = s;
        g_part[(size_t)blockIdx.y*2*FH + FH + n0 + c] = q;
    }
}

// ---------------- combined BN reduce (blocks 0-511: H, 512-1023: Hend) ----------------
__global__ void k_bn_both(const float* __restrict__ gm_h, const float* __restrict__ bt_h,
                          const float* __restrict__ gm_t, const float* __restrict__ bt_t)
{
    int cb = blockIdx.x;
    int mode = (cb >= FH);
    int c = mode ? cb - FH : cb;
    int t = threadIdx.x;
    int nblocks = mode ? (NGRAPH/128) : (NNODES/128);
    float invN   = mode ? (1.0f/(float)NGRAPH) : (1.0f/(float)NNODES);
    const float* part  = mode ? g_parte : g_part;
    const float* gamma = mode ? gm_t : gm_h;
    const float* beta  = mode ? bt_t : bt_h;

    float s = 0.f, q = 0.f;
    for (int i = t; i < nblocks; i += 256) {
        s += part[(size_t)i*2*FH + c];
        q += part[(size_t)i*2*FH + FH + c];
    }
    __shared__ float rs[256], rq[256];
    rs[t] = s; rq[t] = q; __syncthreads();
    for (int o = 128; o > 0; o >>= 1) {
        if (t < o) { rs[t] += rs[t+o]; rq[t] += rq[t+o]; }
        __syncthreads();
    }
    if (t == 0) {
        float mean = rs[0] * invN;
        float var  = rq[0] * invN - mean*mean;
        float a    = gamma[c] * rsqrtf(var + 1e-5f);
        float bb   = beta[c] - mean * a;
        if (mode) { g_bnAe[c] = a; g_bnBe[c] = bb; }
        else      { g_bnA[c]  = a; g_bnB[c]  = bb; }
    }
}

// ---------------- end branch exp-dot ----------------
__global__ void k_endx(const float* __restrict__ Wxt, const float* __restrict__ bxt)
{
    int g = blockIdx.x;
    int t = threadIdx.x;
    float s = 0.f;
    for (int k = t; k < FH; k += 128) {
        float v = fmaxf(fmaf(g_Hend[(size_t)g*FH + k], g_bnAe[k], g_bnBe[k]), 0.f);
        s = fmaf(v, Wxt[k], s);
    }
    __shared__ float red[128];
    red[t] = s; __syncthreads();
    for (int o = 64; o > 0; o >>= 1) {
        if (t < o) red[t] += red[t+o];
        __syncthreads();
    }
    if (t == 0) g_Xxe[g] = expf(red[0] + bxt[0]);
}

// ===== GEMM2 (1-term): tile 128x192, warp grid 2Mx4N (warp 64x48), 3-stage, 2 CTA/SM =====
#define STG2 25600   // A 10240 | B 15360

__global__ __launch_bounds__(256,2) void k_gemm2_mma(const float* __restrict__ bx,
                                                     float* __restrict__ out)
{
    extern __shared__ char sb[];
    __shared__ float s_sa[FH], s_sb[FH], s_bx[DOUT];
    __shared__ float srow[4][128];
    __shared__ float s_inv[4];
    const int tid = threadIdx.x, lane = tid & 31, wid = tid >> 5;
    const int wm = wid >> 2, wn = wid & 3;          // 2 M-warps(64 rows) x 4 N-warps(48 cols)
    const int m0 = blockIdx.x * 128;
    const uint32_t sbu = smem_u32(sb);

    for (int i = tid; i < FH; i += 256) { s_sa[i] = g_bnA[i]; s_sb[i] = g_bnB[i]; }
    if (tid < DOUT) s_bx[tid] = bx[tid];
    __syncthreads();

    float acc[4][6][4];
#pragma unroll
    for (int a=0;a<4;a++)
#pragma unroll
        for (int b=0;b<6;b++)
#pragma unroll
            for (int d=0;d<4;d++) acc[a][b][d]=0.f;

    const uint32_t a_lo = (uint32_t)((lane & 15)*SA + (lane >> 4)*16);
    const int bg = lane >> 3;
    const uint32_t b_lo = (uint32_t)(((((bg>>1)<<3) + (lane&7))*SA) + (bg&1)*16);

    uint4 va[2];
    auto loadA = [&](int ks){
        const int k0 = ks*32;
#pragma unroll
        for (int i=0;i<2;i++){
            int idx = tid + i*256;           // 128 rows x 4 chunks = 512
            int r = idx >> 2, ch = idx & 3;
            va[i] = *(const uint4*)(g_H + (size_t)(m0+r)*FH + k0 + (ch<<3));
        }
    };
    auto stsA = [&](int ks){
        const int s = ks % 3, k0 = ks*32;
#pragma unroll
        for (int i=0;i<2;i++){
            int idx = tid + i*256;
            int r = idx >> 2, ch = idx & 3;
            uint32_t w[4];
            const uint32_t* vw = (const uint32_t*)&va[i];
#pragma unroll
            for (int j=0;j<4;j++){
                int k = k0 + (ch<<3) + j*2;
                float f0 = __uint_as_float((vw[j] & 0xffffu) << 16);
                float f1 = __uint_as_float(vw[j] & 0xffff0000u);
                float x0 = fmaxf(fmaf(f0, s_sa[k],   s_sb[k]),   0.f);
                float x1 = fmaxf(fmaf(f1, s_sa[k+1], s_sb[k+1]), 0.f);
                w[j] = pack2(f2b(x0), f2b(x1));
            }
            *(uint4*)(sb + s*STG2 + r*SA + (ch<<4)) = make_uint4(w[0],w[1],w[2],w[3]);
        }
    };
    auto issueB = [&](int ks){
        const int s = ks % 3, k0 = ks*32;
        const uint32_t Bh = sbu + s*STG2 + 10240;
#pragma unroll
        for (int j=0;j<3;j++){
            int idx = tid + j*256;           // 192 rows x 4 chunks = 768
            int r = idx >> 2, ch = idx & 3;
            CPA16(Bh + (uint32_t)(r*SA + (ch<<4)), g_Wxhi + (size_t)r*FH + k0 + (ch<<3));
        }
    };
    auto compute = [&](int s){
        const uint32_t Ah = sbu + s*STG2, Bh = Ah + 10240;
#pragma unroll
        for (int kk=0; kk<2; kk++){
            uint32_t aH[4][4];
#pragma unroll
            for (int mt=0; mt<4; mt++){
                uint32_t off = (uint32_t)((wm*64 + mt*16)*SA + kk*32) + a_lo;
                ldmA(aH[mt], Ah + off);
            }
#pragma unroll
            for (int nb=0; nb<3; nb++){
                uint32_t boff = (uint32_t)((wn*48 + nb*16)*SA + kk*32) + b_lo;
                uint32_t bH[4];
                ldmB(bH, Bh + boff);
#pragma unroll
                for (int h=0; h<2; h++)
#pragma unroll
                    for (int mt=0; mt<4; mt++)
                        mma_bf(acc[mt][nb*2+h], aH[mt], &bH[h*2]);
            }
        }
    };

    loadA(0); issueB(0); CPC(); stsA(0);
    loadA(1); issueB(1); CPC(); stsA(1);
    for (int ks=0; ks<16; ks++){
        if (ks < 14) CPW1(); else CPW0();
        __syncthreads();
        if (ks < 14){ loadA(ks+2); issueB(ks+2); CPC(); }
        compute(ks % 3);
        if (ks < 14) stsA(ks+2);
    }
    __syncthreads();

    // ---- fused epilogue: exp(+bias), per-graph softmax sums, normalize, scatter ----
    float rsum[4][2] = {{0.f,0.f},{0.f,0.f},{0.f,0.f},{0.f,0.f}};
#pragma unroll
    for (int mt=0; mt<4; mt++)
#pragma unroll
        for (int nt=0; nt<6; nt++){
            int cg = wn*48 + nt*8 + ((lane&3)<<1);
            if (cg < DOUT){
                float e0 = expf(acc[mt][nt][0] + s_bx[cg]);
                float e1 = expf(acc[mt][nt][1] + s_bx[cg+1]);
                float e2 = expf(acc[mt][nt][2] + s_bx[cg]);
                float e3 = expf(acc[mt][nt][3] + s_bx[cg+1]);
                acc[mt][nt][0]=e0; acc[mt][nt][1]=e1;
                acc[mt][nt][2]=e2; acc[mt][nt][3]=e3;
                rsum[mt][0] += e0+e1;
                rsum[mt][1] += e2+e3;
            }
        }
#pragma unroll
    for (int mt=0;mt<4;mt++){
        rsum[mt][0] += __shfl_xor_sync(0xffffffffu, rsum[mt][0], 1);
        rsum[mt][0] += __shfl_xor_sync(0xffffffffu, rsum[mt][0], 2);
        rsum[mt][1] += __shfl_xor_sync(0xffffffffu, rsum[mt][1], 1);
        rsum[mt][1] += __shfl_xor_sync(0xffffffffu, rsum[mt][1], 2);
    }
    if ((lane&3)==0){
#pragma unroll
        for (int mt=0;mt<4;mt++){
            int r = wm*64 + mt*16 + (lane>>2);
            srow[wn][r]   = rsum[mt][0];
            srow[wn][r+8] = rsum[mt][1];
        }
    }
    __syncthreads();
    if (wid == 0){
#pragma unroll
        for (int g=0; g<4; g++){
            float v = srow[0][g*32 + lane] + srow[1][g*32 + lane]
                    + srow[2][g*32 + lane] + srow[3][g*32 + lane];
#pragma unroll
            for (int o=16;o;o>>=1) v += __shfl_xor_sync(0xffffffffu, v, o);
            if (lane == 0){
                int G = (m0>>5) + g;
                float xe = g_Xxe[G];
                float tot = v + xe;
                s_inv[g] = 1.0f/tot;
                out[APPEND_SZ + CONNECT_SZ + G] = xe/tot;
            }
        }
    }
    __syncthreads();
#pragma unroll
    for (int mt=0;mt<4;mt++){
        const float f = s_inv[wm*2 + (mt>>1)];
#pragma unroll
        for (int nt=0;nt<6;nt++){
            int cg = wn*48 + nt*8 + ((lane&3)<<1);
            if (cg < DOUT){
                int R0 = m0 + wm*64 + mt*16 + (lane>>2);
                int R1 = R0 + 8;
                float2 v0 = make_float2(acc[mt][nt][0]*f, acc[mt][nt][1]*f);
                float2 v1 = make_float2(acc[mt][nt][2]*f, acc[mt][nt][3]*f);
                if (cg < NB){
                    *(float2*)(out + APPEND_SZ + (size_t)R0*NB + cg) = v0;
                    *(float2*)(out + APPEND_SZ + (size_t)R1*NB + cg) = v1;
                } else {
                    *(float2*)(out + (size_t)R0*(DOUT-NB) + (cg-NB)) = v0;
                    *(float2*)(out + (size_t)R1*(DOUT-NB) + (cg-NB)) = v1;
                }
            }
        }
    }
}

// ---------------- launch ----------------
extern "C" void kernel_launch(void* const* d_in, const int* in_sizes, int n_in,
                              void* d_out, int out_size)
{
    const float* X    = (const float*)d_in[0];
    const float* W_h  = (const float*)d_in[3];
    const float* gm_h = (const float*)d_in[4];
    const float* bt_h = (const float*)d_in[5];
    const float* W_ht = (const float*)d_in[6];
    const float* gm_t = (const float*)d_in[7];
    const float* bt_t = (const float*)d_in[8];
    const float* W_x  = (const float*)d_in[9];
    const float* b_x  = (const float*)d_in[10];
    const float* W_xt = (const float*)d_in[11];
    const float* b_xt = (const float*)d_in[12];
    float* out = (float*)d_out;

    cudaFuncSetAttribute(k_pre_mma,   cudaFuncAttributeMaxDynamicSharedMemorySize, 2*STGP);
    cudaFuncSetAttribute(k_gemm1_mma, cudaFuncAttributeMaxDynamicSharedMemorySize, 4*STG1);
    cudaFuncSetAttribute(k_gemm2_mma, cudaFuncAttributeMaxDynamicSharedMemorySize, 3*STG2);

    // weight conversion + per-graph mean + X bf16 (one merged grid)
    k_prep<<<1024 + NGRAPH, 256>>>(X, W_h, W_x, W_ht);

    // [Hc | Hend] = Xend @ [Wh2 ; Wht]^T (2-term) with fused end-branch stats
    k_pre_mma<<<dim3(4, NGRAPH/128), 256, 2*STGP>>>();

    // H = X @ W1^T + Hc[g]  (bf16 store) + fused BN partial stats (K=256)
    k_gemm1_mma<<<dim3(4, NNODES/128), 256, 4*STG1>>>();

    // both BN reductions in one launch
    k_bn_both<<<2*FH, 256>>>(gm_h, bt_h, gm_t, bt_t);

    // end-branch exp-dot
    k_endx<<<NGRAPH, 128>>>(W_xt, b_xt);

    // X_x GEMM (bf16) + exp + per-graph softmax + scatter
    k_gemm2_mma<<<NNODES/128, 256, 3*STG2>>>(b_x, out);
}